// round 2
// baseline (speedup 1.0000x reference)
#include <cuda_runtime.h>
#include <math_constants.h>

#define N_NODES 50000
#define NEDGE   1600000
#define HDIM    128
#define NUC     49232
#define NMC     512
#define NSC     256

// ---------------- scratch (device globals; no allocation allowed) ----------------
__device__ float g_X[(size_t)N_NODES * HDIM];   // layer input / activated output (25.6 MB)
__device__ float g_H[(size_t)N_NODES * HDIM];   // h = X @ W for current layer    (25.6 MB)
__device__ float g_el[N_NODES];
__device__ float g_er[N_NODES];
__device__ float g_ebuf[NEDGE];                 // per-edge scratch (attn numerators)
__device__ int   g_deg[N_NODES];
__device__ int   g_rowptr[N_NODES + 1];
__device__ int   g_pos[N_NODES];
__device__ int   g_esrc[NEDGE];                 // src ids sorted by dst
__device__ float g_T[NMC * HDIM];               // model @ Wb

// ---------------- CSR build ----------------
__global__ void k_zero_deg() {
    int i = blockIdx.x * blockDim.x + threadIdx.x;
    if (i < N_NODES) g_deg[i] = 0;
}

__global__ void k_count(const int* __restrict__ dst) {
    int e = blockIdx.x * blockDim.x + threadIdx.x;
    if (e < NEDGE) atomicAdd(&g_deg[dst[e]], 1);
}

// single-block exclusive scan (warp-shuffle based)
__global__ void k_scan() {
    __shared__ int wsum[32];
    __shared__ int wpre[32];
    __shared__ int s_run;
    int t = threadIdx.x, lane = t & 31, wid = t >> 5;
    if (t == 0) s_run = 0;
    __syncthreads();
    for (int base = 0; base < N_NODES; base += 1024) {
        int idx = base + t;
        int v = (idx < N_NODES) ? g_deg[idx] : 0;
        int incl = v;
        #pragma unroll
        for (int o = 1; o < 32; o <<= 1) {
            int y = __shfl_up_sync(0xffffffffu, incl, o);
            if (lane >= o) incl += y;
        }
        if (lane == 31) wsum[wid] = incl;
        __syncthreads();
        int run = s_run;
        if (wid == 0) {
            int x = wsum[lane];
            int xs = x;
            #pragma unroll
            for (int o = 1; o < 32; o <<= 1) {
                int y = __shfl_up_sync(0xffffffffu, xs, o);
                if (lane >= o) xs += y;
            }
            wpre[lane] = xs - x;
        }
        __syncthreads();
        int inclfull = wpre[wid] + incl;
        if (idx < N_NODES) {
            int ex = run + inclfull - v;
            g_rowptr[idx] = ex;
            g_pos[idx]    = ex;
        }
        __syncthreads();                 // all reads of s_run done before update
        if (t == 1023) s_run = run + inclfull;
        __syncthreads();
    }
    if (t == 0) g_rowptr[N_NODES] = s_run;
}

__global__ void k_scatter(const int* __restrict__ src, const int* __restrict__ dst) {
    int e = blockIdx.x * blockDim.x + threadIdx.x;
    if (e < NEDGE) {
        int p = atomicAdd(&g_pos[dst[e]], 1);
        g_esrc[p] = src[e];
    }
}

// ---------------- GEMM: Y[nrows x 128] = X[nrows x 128] @ W[128 x 128] ----------------
// 128 threads/block, block computes 32 rows x 128 cols. Thread: 8 rows x 4 cols.
// Optional fused epilogue: el[row] = Y[row]@al, er[row] = Y[row]@ar
// (each warp owns 8 full rows: rows (t>>5)*8..+7, cols spread over 32 lanes).
__global__ void k_gemm(const float* __restrict__ X, const float* __restrict__ W,
                       float* __restrict__ Y, int nrows,
                       const float* __restrict__ al, const float* __restrict__ ar) {
    extern __shared__ float smem[];
    float* ws = smem;           // 128*128
    float* xs = smem + 16384;   // 32*128
    int t = threadIdx.x;
    int row0 = blockIdx.x * 32;

    const float4* W4 = (const float4*)W;
    float4* ws4 = (float4*)ws;
    #pragma unroll 4
    for (int i = t; i < 4096; i += 128) ws4[i] = W4[i];

    const float4* X4 = (const float4*)X;
    float4* xs4 = (float4*)xs;
    for (int i = t; i < 1024; i += 128) {
        int r = i >> 5, c = i & 31;
        float4 v = make_float4(0.f, 0.f, 0.f, 0.f);
        if (row0 + r < nrows) v = X4[(size_t)(row0 + r) * 32 + c];
        xs4[i] = v;
    }
    __syncthreads();

    int lane = t & 31;
    int cj = lane * 4;
    int r0 = (t >> 5) * 8;
    float acc[8][4];
    #pragma unroll
    for (int r = 0; r < 8; r++)
        #pragma unroll
        for (int c = 0; c < 4; c++) acc[r][c] = 0.f;

    #pragma unroll 4
    for (int k = 0; k < 128; k++) {
        float4 w4 = *(const float4*)(ws + k * 128 + cj);
        #pragma unroll
        for (int r = 0; r < 8; r++) {
            float xv = xs[(r0 + r) * 128 + k];
            acc[r][0] += xv * w4.x;
            acc[r][1] += xv * w4.y;
            acc[r][2] += xv * w4.z;
            acc[r][3] += xv * w4.w;
        }
    }
    #pragma unroll
    for (int r = 0; r < 8; r++) {
        int row = row0 + r0 + r;
        if (row < nrows)
            *(float4*)(Y + (size_t)row * 128 + cj) =
                make_float4(acc[r][0], acc[r][1], acc[r][2], acc[r][3]);
    }

    // fused attention dot products
    if (al != nullptr) {
        float4 a4 = ((const float4*)al)[lane];
        float4 r4 = ((const float4*)ar)[lane];
        #pragma unroll
        for (int r = 0; r < 8; r++) {
            float pl = acc[r][0] * a4.x + acc[r][1] * a4.y +
                       acc[r][2] * a4.z + acc[r][3] * a4.w;
            float pr = acc[r][0] * r4.x + acc[r][1] * r4.y +
                       acc[r][2] * r4.z + acc[r][3] * r4.w;
            #pragma unroll
            for (int o = 16; o; o >>= 1) {
                pl += __shfl_xor_sync(0xffffffffu, pl, o);
                pr += __shfl_xor_sync(0xffffffffu, pr, o);
            }
            int row = row0 + r0 + r;
            if (lane == 0 && row < nrows) { g_el[row] = pl; g_er[row] = pr; }
        }
    }
}

// ---------------- fused softmax-attention + aggregation, one warp per dst node ----------------
__global__ void k_node(const float* __restrict__ bvec, int do_relu) {
    int gw = (blockIdx.x * blockDim.x + threadIdx.x) >> 5;
    int lane = threadIdx.x & 31;
    if (gw >= N_NODES) return;
    int start = g_rowptr[gw];
    int end   = g_rowptr[gw + 1];
    float eld = g_el[gw];

    // pass 1: raw scores + segment max
    float m = -CUDART_INF_F;
    for (int i = start + lane; i < end; i += 32) {
        int s = g_esrc[i];
        float e = eld + g_er[s];
        e = (e > 0.f) ? e : 0.2f * e;     // leaky_relu 0.2
        g_ebuf[i] = e;
        m = fmaxf(m, e);
    }
    #pragma unroll
    for (int o = 16; o; o >>= 1) m = fmaxf(m, __shfl_xor_sync(0xffffffffu, m, o));

    // pass 2: exp + segment sum
    float ssum = 0.f;
    for (int i = start + lane; i < end; i += 32) {
        float v = __expf(g_ebuf[i] - m);
        g_ebuf[i] = v;
        ssum += v;
    }
    #pragma unroll
    for (int o = 16; o; o >>= 1) ssum += __shfl_xor_sync(0xffffffffu, ssum, o);
    float inv = 1.f / (ssum + 1e-10f);
    __syncwarp();   // make cross-lane g_ebuf writes visible

    // pass 3: weighted gather of h rows; lane owns 4 contiguous cols
    float4 acc = make_float4(0.f, 0.f, 0.f, 0.f);
    const float4* H4 = (const float4*)g_H;
    #pragma unroll 4
    for (int i = start; i < end; i++) {
        float a = g_ebuf[i] * inv;        // broadcast load
        int s = g_esrc[i];                // broadcast load
        float4 hv = H4[(size_t)s * 32 + lane];
        acc.x += a * hv.x; acc.y += a * hv.y; acc.z += a * hv.z; acc.w += a * hv.w;
    }

    float4 b4 = ((const float4*)bvec)[lane];
    float4 o4 = make_float4(acc.x + b4.x, acc.y + b4.y, acc.z + b4.z, acc.w + b4.w);
    if (do_relu) {
        o4.x = fmaxf(o4.x, 0.f); o4.y = fmaxf(o4.y, 0.f);
        o4.z = fmaxf(o4.z, 0.f); o4.w = fmaxf(o4.w, 0.f);
    }
    ((float4*)g_X)[(size_t)gw * 32 + lane] = o4;
}

// ---------------- bilinear head: scores[m][s] = dot(T[m], server[s]) + bb ----------------
__global__ void k_scores(const float* __restrict__ bb, float* __restrict__ out) {
    __shared__ __align__(16) float Tm[16][132];
    __shared__ __align__(16) float Ss[16][132];
    int tx = threadIdx.x;       // s within tile
    int ty = threadIdx.y;       // m within tile
    int m0 = blockIdx.x * 16, s0 = blockIdx.y * 16;
    int t = ty * 16 + tx;
    for (int i = t; i < 512; i += 256) {
        int r = i >> 5, c = i & 31;
        float4 v = ((const float4*)g_T)[(size_t)(m0 + r) * 32 + c];
        *(float4*)&Tm[r][c * 4] = v;
        float4 w = ((const float4*)g_X)[(size_t)(NUC + NMC + s0 + r) * 32 + c];
        *(float4*)&Ss[r][c * 4] = w;
    }
    __syncthreads();
    float4 acc = make_float4(0.f, 0.f, 0.f, 0.f);
    #pragma unroll 8
    for (int k = 0; k < 32; k++) {
        float4 a = *(const float4*)&Tm[ty][k * 4];
        float4 b = *(const float4*)&Ss[tx][k * 4];
        acc.x += a.x * b.x; acc.y += a.y * b.y;
        acc.z += a.z * b.z; acc.w += a.w * b.w;
    }
    out[(m0 + ty) * NSC + (s0 + tx)] = acc.x + acc.y + acc.z + acc.w + bb[0];
}

// ---------------- host ----------------
extern "C" void kernel_launch(void* const* d_in, const int* in_sizes, int n_in,
                              void* d_out, int out_size) {
    const float* x   = (const float*)d_in[0];
    const int*   ei  = (const int*)  d_in[1];
    const int*   src = ei;
    const int*   dst = ei + NEDGE;
    const float* W1  = (const float*)d_in[2];
    const float* al1 = (const float*)d_in[3];
    const float* ar1 = (const float*)d_in[4];
    const float* b1  = (const float*)d_in[5];
    const float* W2  = (const float*)d_in[6];
    const float* al2 = (const float*)d_in[7];
    const float* ar2 = (const float*)d_in[8];
    const float* b2  = (const float*)d_in[9];
    const float* W3  = (const float*)d_in[10];
    const float* al3 = (const float*)d_in[11];
    const float* ar3 = (const float*)d_in[12];
    const float* b3  = (const float*)d_in[13];
    const float* Wb  = (const float*)d_in[14];
    const float* bb  = (const float*)d_in[15];
    float* out = (float*)d_out;

    void *pX_, *pH_, *pT_;
    cudaGetSymbolAddress(&pX_, g_X);
    cudaGetSymbolAddress(&pH_, g_H);
    cudaGetSymbolAddress(&pT_, g_T);
    float* pX = (float*)pX_;
    float* pH = (float*)pH_;
    float* pT = (float*)pT_;

    cudaFuncSetAttribute(k_gemm, cudaFuncAttributeMaxDynamicSharedMemorySize, 81920);

    // CSR build (dst-sorted edge list)
    k_zero_deg<<<(N_NODES + 255) / 256, 256>>>();
    k_count  <<<(NEDGE + 255) / 256, 256>>>(dst);
    k_scan   <<<1, 1024>>>();
    k_scatter<<<(NEDGE + 255) / 256, 256>>>(src, dst);

    int warpgrid = (N_NODES * 32 + 255) / 256;
    int gemmgrid = (N_NODES + 31) / 32;

    // layer 1
    k_gemm<<<gemmgrid, 128, 81920>>>(x, W1, pH, N_NODES, al1, ar1);
    k_node<<<warpgrid, 256>>>(b1, 1);
    // layer 2
    k_gemm<<<gemmgrid, 128, 81920>>>(pX, W2, pH, N_NODES, al2, ar2);
    k_node<<<warpgrid, 256>>>(b2, 1);
    // layer 3 (no relu)
    k_gemm<<<gemmgrid, 128, 81920>>>(pX, W3, pH, N_NODES, al3, ar3);
    k_node<<<warpgrid, 256>>>(b3, 0);

    // bilinear head
    k_gemm<<<(NMC + 31) / 32, 128, 81920>>>(pX + (size_t)NUC * HDIM, Wb, pT, NMC, nullptr, nullptr);
    k_scores<<<dim3(NMC / 16, NSC / 16), dim3(16, 16)>>>(bb, out);
}

// round 3
// speedup vs baseline: 1.3145x; 1.3145x over previous
#include <cuda_runtime.h>
#include <cuda_fp16.h>
#include <math_constants.h>

#define N_NODES 50000
#define NEDGE   1600000
#define HDIM    128
#define NUC     49232
#define NMC     512
#define NSC     256
#define NB      196      // scan blocks: 196*256 = 50176 >= N_NODES

// ---------------- scratch (device globals; no allocation allowed) ----------------
__device__ float  g_X[(size_t)N_NODES * HDIM];   // layer input / activated output
__device__ __half g_Hh[(size_t)N_NODES * HDIM];  // h = X @ W, fp16 for gather path
__device__ float  g_el[N_NODES];
__device__ float  g_er[N_NODES];
__device__ float  g_ebuf[NEDGE];                 // per-edge raw scores
__device__ int    g_deg[N_NODES];
__device__ int    g_rowptr[N_NODES + 1];
__device__ int    g_pos[N_NODES];
__device__ int    g_esrc[NEDGE];                 // src ids sorted by dst
__device__ int    g_bsum[NB];
__device__ int    g_boff[NB];
__device__ float  g_T[NMC * HDIM];               // model @ Wb

// ---------------- CSR build ----------------
__global__ void k_zero_deg() {
    int i = blockIdx.x * blockDim.x + threadIdx.x;
    if (i < N_NODES) g_deg[i] = 0;
}

__global__ void k_count(const int* __restrict__ dst) {
    int e = blockIdx.x * blockDim.x + threadIdx.x;
    if (e < NEDGE) atomicAdd(&g_deg[dst[e]], 1);
}

// multi-block exclusive scan, stage 1: per-block exclusive scan + block sums
__global__ void k_scan1() {
    __shared__ int wsum[8];
    __shared__ int wpre[8];
    int t = threadIdx.x, lane = t & 31, w = t >> 5;
    int idx = blockIdx.x * 256 + t;
    int v = (idx < N_NODES) ? g_deg[idx] : 0;
    int incl = v;
    #pragma unroll
    for (int o = 1; o < 32; o <<= 1) {
        int y = __shfl_up_sync(0xffffffffu, incl, o);
        if (lane >= o) incl += y;
    }
    if (lane == 31) wsum[w] = incl;
    __syncthreads();
    if (t < 8) {
        int x = wsum[t], xs = x;
        #pragma unroll
        for (int o = 1; o < 8; o <<= 1) {
            int y = __shfl_up_sync(0xffu, xs, o);
            if (t >= o) xs += y;
        }
        wpre[t] = xs - x;
        if (t == 7) g_bsum[blockIdx.x] = xs;
    }
    __syncthreads();
    if (idx < N_NODES) g_rowptr[idx] = wpre[w] + incl - v;   // local exclusive
}

// stage 2: scan the 196 block sums
__global__ void k_scan2() {
    __shared__ int wsum[8];
    __shared__ int wpre[8];
    int t = threadIdx.x, lane = t & 31, w = t >> 5;
    int v = (t < NB) ? g_bsum[t] : 0;
    int incl = v;
    #pragma unroll
    for (int o = 1; o < 32; o <<= 1) {
        int y = __shfl_up_sync(0xffffffffu, incl, o);
        if (lane >= o) incl += y;
    }
    if (lane == 31) wsum[w] = incl;
    __syncthreads();
    if (t < 8) {
        int x = wsum[t], xs = x;
        #pragma unroll
        for (int o = 1; o < 8; o <<= 1) {
            int y = __shfl_up_sync(0xffu, xs, o);
            if (t >= o) xs += y;
        }
        wpre[t] = xs - x;
    }
    __syncthreads();
    if (t < NB) g_boff[t] = wpre[w] + incl - v;
    if (t == 0) g_rowptr[N_NODES] = NEDGE;
}

// stage 3: add block offsets
__global__ void k_scan3() {
    int t = threadIdx.x;
    int idx = blockIdx.x * 256 + t;
    if (idx < N_NODES) {
        int r = g_rowptr[idx] + g_boff[blockIdx.x];
        g_rowptr[idx] = r;
        g_pos[idx]    = r;
    }
}

__global__ void k_scatter(const int* __restrict__ src, const int* __restrict__ dst) {
    int e = blockIdx.x * blockDim.x + threadIdx.x;
    if (e < NEDGE) {
        int p = atomicAdd(&g_pos[dst[e]], 1);
        g_esrc[p] = src[e];
    }
}

// ---------------- GEMM: H[nrows x 128] = X[nrows x 128] @ W[128 x 128] ----------------
// 256 threads/block, block computes 64 rows x 128 cols. Thread: 8 rows x 4 cols.
// Output: fp16 Yh (gather path) and/or fp32 Yf (head path).
// Fused epilogue: el[row]=Y[row]@al, er[row]=Y[row]@ar (warp owns 8 full rows).
__global__ void k_gemm(const float* __restrict__ X, const float* __restrict__ W,
                       float* __restrict__ Yf, __half* __restrict__ Yh, int nrows,
                       const float* __restrict__ al, const float* __restrict__ ar) {
    extern __shared__ float smem[];
    float* ws = smem;           // 128*128 = 64 KB
    float* xs = smem + 16384;   // 64*128 = 32 KB
    int t = threadIdx.x;
    int row0 = blockIdx.x * 64;

    const float4* W4 = (const float4*)W;
    float4* ws4 = (float4*)ws;
    #pragma unroll 4
    for (int i = t; i < 4096; i += 256) ws4[i] = W4[i];

    const float4* X4 = (const float4*)X;
    float4* xs4 = (float4*)xs;
    #pragma unroll 2
    for (int i = t; i < 2048; i += 256) {
        int r = i >> 5, c = i & 31;
        float4 v = make_float4(0.f, 0.f, 0.f, 0.f);
        if (row0 + r < nrows) v = X4[(size_t)(row0 + r) * 32 + c];
        xs4[i] = v;
    }
    __syncthreads();

    int lane = t & 31;
    int cj = lane * 4;
    int r0 = (t >> 5) * 8;
    float acc[8][4];
    #pragma unroll
    for (int r = 0; r < 8; r++)
        #pragma unroll
        for (int c = 0; c < 4; c++) acc[r][c] = 0.f;

    #pragma unroll 2
    for (int kk = 0; kk < 128; kk += 4) {
        float4 xv[8];
        #pragma unroll
        for (int r = 0; r < 8; r++)
            xv[r] = *(const float4*)(xs + (r0 + r) * 128 + kk);
        #pragma unroll
        for (int q = 0; q < 4; q++) {
            float4 w4 = *(const float4*)(ws + (kk + q) * 128 + cj);
            #pragma unroll
            for (int r = 0; r < 8; r++) {
                float xvq = (q == 0) ? xv[r].x : (q == 1) ? xv[r].y : (q == 2) ? xv[r].z : xv[r].w;
                acc[r][0] += xvq * w4.x;
                acc[r][1] += xvq * w4.y;
                acc[r][2] += xvq * w4.z;
                acc[r][3] += xvq * w4.w;
            }
        }
    }

    #pragma unroll
    for (int r = 0; r < 8; r++) {
        int row = row0 + r0 + r;
        if (row < nrows) {
            if (Yh) {
                __half2 p0 = __floats2half2_rn(acc[r][0], acc[r][1]);
                __half2 p1 = __floats2half2_rn(acc[r][2], acc[r][3]);
                unsigned u0 = *(unsigned*)&p0;
                unsigned u1 = *(unsigned*)&p1;
                ((uint2*)Yh)[(size_t)row * 32 + lane] = make_uint2(u0, u1);
            }
            if (Yf)
                *(float4*)(Yf + (size_t)row * 128 + cj) =
                    make_float4(acc[r][0], acc[r][1], acc[r][2], acc[r][3]);
        }
    }

    // fused attention dot products (fp32 accumulators -> exact-ish el/er)
    if (al != nullptr) {
        float4 a4 = ((const float4*)al)[lane];
        float4 r4 = ((const float4*)ar)[lane];
        #pragma unroll
        for (int r = 0; r < 8; r++) {
            float pl = acc[r][0] * a4.x + acc[r][1] * a4.y +
                       acc[r][2] * a4.z + acc[r][3] * a4.w;
            float pr = acc[r][0] * r4.x + acc[r][1] * r4.y +
                       acc[r][2] * r4.z + acc[r][3] * r4.w;
            #pragma unroll
            for (int o = 16; o; o >>= 1) {
                pl += __shfl_xor_sync(0xffffffffu, pl, o);
                pr += __shfl_xor_sync(0xffffffffu, pr, o);
            }
            int row = row0 + r0 + r;
            if (lane == 0 && row < nrows) { g_el[row] = pl; g_er[row] = pr; }
        }
    }
}

// ---------------- fused softmax-attention + aggregation, one warp per dst node ----------------
__global__ void k_node(const float* __restrict__ bvec, int do_relu) {
    int gw = (blockIdx.x * blockDim.x + threadIdx.x) >> 5;
    int lane = threadIdx.x & 31;
    if (gw >= N_NODES) return;
    int start = g_rowptr[gw];
    int end   = g_rowptr[gw + 1];
    float eld = g_el[gw];

    // pass A: raw scores + online max/sum
    float m = -CUDART_INF_F;
    float s = 0.f;
    for (int i = start + lane; i < end; i += 32) {
        int sv = g_esrc[i];
        float e = eld + g_er[sv];
        e = (e > 0.f) ? e : 0.2f * e;     // leaky_relu 0.2
        g_ebuf[i] = e;
        float mn = fmaxf(m, e);
        s = s * __expf(m - mn) + __expf(e - mn);
        m = mn;
    }
    float M = m;
    #pragma unroll
    for (int o = 16; o; o >>= 1) M = fmaxf(M, __shfl_xor_sync(0xffffffffu, M, o));
    float sadj = s * __expf(m - M);       // m=-inf,s=0 -> 0
    #pragma unroll
    for (int o = 16; o; o >>= 1) sadj += __shfl_xor_sync(0xffffffffu, sadj, o);
    float inv = 1.f / (sadj + 1e-10f);
    __syncwarp();   // make cross-lane g_ebuf writes visible

    // pass B: weighted fp16 gather; lane owns 4 contiguous cols
    float4 acc = make_float4(0.f, 0.f, 0.f, 0.f);
    const uint2* H2 = (const uint2*)g_Hh;
    #pragma unroll 4
    for (int i = start; i < end; i++) {
        float a = __expf(g_ebuf[i] - M) * inv;   // broadcast load
        int sv = g_esrc[i];                      // broadcast load
        uint2 raw = H2[(size_t)sv * 32 + lane];
        __half2 h0 = *(__half2*)&raw.x;
        __half2 h1 = *(__half2*)&raw.y;
        float2 f0 = __half22float2(h0);
        float2 f1 = __half22float2(h1);
        acc.x += a * f0.x; acc.y += a * f0.y;
        acc.z += a * f1.x; acc.w += a * f1.y;
    }

    float4 b4 = ((const float4*)bvec)[lane];
    float4 o4 = make_float4(acc.x + b4.x, acc.y + b4.y, acc.z + b4.z, acc.w + b4.w);
    if (do_relu) {
        o4.x = fmaxf(o4.x, 0.f); o4.y = fmaxf(o4.y, 0.f);
        o4.z = fmaxf(o4.z, 0.f); o4.w = fmaxf(o4.w, 0.f);
    }
    ((float4*)g_X)[(size_t)gw * 32 + lane] = o4;
}

// ---------------- bilinear head: scores[m][s] = dot(T[m], server[s]) + bb ----------------
__global__ void k_scores(const float* __restrict__ bb, float* __restrict__ out) {
    __shared__ __align__(16) float Tm[16][132];
    __shared__ __align__(16) float Ss[16][132];
    int tx = threadIdx.x;       // s within tile
    int ty = threadIdx.y;       // m within tile
    int m0 = blockIdx.x * 16, s0 = blockIdx.y * 16;
    int t = ty * 16 + tx;
    for (int i = t; i < 512; i += 256) {
        int r = i >> 5, c = i & 31;
        float4 v = ((const float4*)g_T)[(size_t)(m0 + r) * 32 + c];
        *(float4*)&Tm[r][c * 4] = v;
        float4 w = ((const float4*)g_X)[(size_t)(NUC + NMC + s0 + r) * 32 + c];
        *(float4*)&Ss[r][c * 4] = w;
    }
    __syncthreads();
    float4 acc = make_float4(0.f, 0.f, 0.f, 0.f);
    #pragma unroll 8
    for (int k = 0; k < 32; k++) {
        float4 a = *(const float4*)&Tm[ty][k * 4];
        float4 b = *(const float4*)&Ss[tx][k * 4];
        acc.x += a.x * b.x; acc.y += a.y * b.y;
        acc.z += a.z * b.z; acc.w += a.w * b.w;
    }
    out[(m0 + ty) * NSC + (s0 + tx)] = acc.x + acc.y + acc.z + acc.w + bb[0];
}

// ---------------- host ----------------
extern "C" void kernel_launch(void* const* d_in, const int* in_sizes, int n_in,
                              void* d_out, int out_size) {
    const float* x   = (const float*)d_in[0];
    const int*   ei  = (const int*)  d_in[1];
    const int*   src = ei;
    const int*   dst = ei + NEDGE;
    const float* W1  = (const float*)d_in[2];
    const float* al1 = (const float*)d_in[3];
    const float* ar1 = (const float*)d_in[4];
    const float* b1  = (const float*)d_in[5];
    const float* W2  = (const float*)d_in[6];
    const float* al2 = (const float*)d_in[7];
    const float* ar2 = (const float*)d_in[8];
    const float* b2  = (const float*)d_in[9];
    const float* W3  = (const float*)d_in[10];
    const float* al3 = (const float*)d_in[11];
    const float* ar3 = (const float*)d_in[12];
    const float* b3  = (const float*)d_in[13];
    const float* Wb  = (const float*)d_in[14];
    const float* bb  = (const float*)d_in[15];
    float* out = (float*)d_out;

    void *pX_, *pHh_, *pT_;
    cudaGetSymbolAddress(&pX_, g_X);
    cudaGetSymbolAddress(&pHh_, g_Hh);
    cudaGetSymbolAddress(&pT_, g_T);
    float*  pX = (float*)pX_;
    __half* pH = (__half*)pHh_;
    float*  pT = (float*)pT_;

    cudaFuncSetAttribute(k_gemm, cudaFuncAttributeMaxDynamicSharedMemorySize, 98304);

    // CSR build (dst-sorted edge list)
    k_zero_deg<<<NB, 256>>>();
    k_count  <<<(NEDGE + 255) / 256, 256>>>(dst);
    k_scan1  <<<NB, 256>>>();
    k_scan2  <<<1, 256>>>();
    k_scan3  <<<NB, 256>>>();
    k_scatter<<<(NEDGE + 255) / 256, 256>>>(src, dst);

    int warpgrid = (N_NODES * 32 + 255) / 256;
    int gemmgrid = (N_NODES + 63) / 64;

    // layer 1
    k_gemm<<<gemmgrid, 256, 98304>>>(x, W1, nullptr, pH, N_NODES, al1, ar1);
    k_node<<<warpgrid, 256>>>(b1, 1);
    // layer 2
    k_gemm<<<gemmgrid, 256, 98304>>>(pX, W2, nullptr, pH, N_NODES, al2, ar2);
    k_node<<<warpgrid, 256>>>(b2, 1);
    // layer 3 (no relu)
    k_gemm<<<gemmgrid, 256, 98304>>>(pX, W3, nullptr, pH, N_NODES, al3, ar3);
    k_node<<<warpgrid, 256>>>(b3, 0);

    // bilinear head
    k_gemm<<<(NMC + 63) / 64, 256, 98304>>>(pX + (size_t)NUC * HDIM, Wb, pT, nullptr, NMC,
                                            nullptr, nullptr);
    k_scores<<<dim3(NMC / 16, NSC / 16), dim3(16, 16)>>>(bb, out);
}